// round 3
// baseline (speedup 1.0000x reference)
#include <cuda_runtime.h>
#include <math.h>

#define IC 128
#define NC 5
#define DD 153
#define DP 160      // padded capsule dim
#define CD 765
#define CDP 768     // padded row stride for GEMM outputs / Wp
#define KD 768
#define NQV 256
#define EPSF 1e-8f
#define NCHUNK 3    // d-chunks in pass A
#define DCH 51      // DD / NCHUNK

__device__ __align__(16) float g_hm[IC * CDP];      // hat_m (padded stride)
__device__ __align__(16) float g_hq[NQV * CDP];     // hat_q (padded stride)
__device__ __align__(16) float g_hmT[NC * DD * IC]; // [c][d][i]
__device__ __align__(16) float g_mean[NC * IC];     // [c][i]
__device__ __align__(16) float g_norm[NC * IC];     // [c][i]
__device__ __align__(16) float g_Wp[KD * CDP];      // zero-padded W

__device__ __forceinline__ float warp_sum(float v) {
#pragma unroll
  for (int o = 16; o; o >>= 1) v += __shfl_xor_sync(0xffffffffu, v, o);
  return v;
}

// ---------------------------------------------------------------------------
// Pad W [768][765] -> Wp [768][768]
// ---------------------------------------------------------------------------
__global__ __launch_bounds__(256) void wpad_kernel(const float* __restrict__ W,
                                                   float* __restrict__ Wp) {
  int idx = blockIdx.x * 256 + threadIdx.x;
  if (idx < KD * CDP) {
    int k = idx / CDP, c = idx - k * CDP;
    Wp[idx] = (c < CD) ? W[k * CD + c] : 0.f;
  }
}

// ---------------------------------------------------------------------------
// Fused GEMM: rows 0..127 = m, 128..383 = q.  out = A @ Wp + b
// BM=32, BN=64, BK=32, 256 threads, 2x4 register tile. Grid (12,12).
// ---------------------------------------------------------------------------
#define BM 32
#define BN 64
#define BK 32

__global__ __launch_bounds__(256) void gemm_kernel(
    const float* __restrict__ Am, const float* __restrict__ Aq,
    const float* __restrict__ Wp, const float* __restrict__ bias,
    float* __restrict__ Om, float* __restrict__ Oq) {
  __shared__ float As[BK][BM + 1];
  __shared__ float Bs[BK][BN];
  const int t = threadIdx.x;
  const int row0 = blockIdx.y * BM;
  const int c0 = blockIdx.x * BN;

  const float* A;
  float* O;
  if (row0 < IC) { A = Am + row0 * KD; O = Om + row0 * CDP; }
  else           { A = Aq + (row0 - IC) * KD; O = Oq + (row0 - IC) * CDP; }

  const int ar = t >> 3, akc = (t & 7) << 2;
  const int br = t >> 4, bc = (t & 15) << 2;
  const int ty = t >> 4, tx = t & 15;

  float acc[2][4] = {};

  for (int k0 = 0; k0 < KD; k0 += BK) {
    float4 av = *(const float4*)(A + ar * KD + k0 + akc);
    As[akc + 0][ar] = av.x;
    As[akc + 1][ar] = av.y;
    As[akc + 2][ar] = av.z;
    As[akc + 3][ar] = av.w;
    *(float4*)&Bs[br][bc]      = *(const float4*)(Wp + (k0 + br) * CDP + c0 + bc);
    *(float4*)&Bs[br + 16][bc] = *(const float4*)(Wp + (k0 + br + 16) * CDP + c0 + bc);
    __syncthreads();
#pragma unroll
    for (int kk = 0; kk < BK; ++kk) {
      float a0 = As[kk][ty];
      float a1 = As[kk][ty + 16];
      float4 b = *(const float4*)&Bs[kk][tx << 2];
      acc[0][0] += a0 * b.x; acc[0][1] += a0 * b.y;
      acc[0][2] += a0 * b.z; acc[0][3] += a0 * b.w;
      acc[1][0] += a1 * b.x; acc[1][1] += a1 * b.y;
      acc[1][2] += a1 * b.z; acc[1][3] += a1 * b.w;
    }
    __syncthreads();
  }

#pragma unroll
  for (int rr = 0; rr < 2; ++rr) {
    int lr = ty + rr * 16;
#pragma unroll
    for (int j = 0; j < 4; ++j) {
      int c = c0 + (tx << 2) + j;
      if (c < CD) O[lr * CDP + c] = acc[rr][j] + bias[c];
    }
  }
}

// ---------------------------------------------------------------------------
// Stats: per (i,c) mean + centered norm; build hmT [c][d][i].
// One warp per (i,c).
// ---------------------------------------------------------------------------
__global__ __launch_bounds__(256) void stats_kernel(
    const float* __restrict__ hm, float* __restrict__ hmT,
    float* __restrict__ meanA, float* __restrict__ normA) {
  int g = blockIdx.x * 8 + (threadIdx.x >> 5);
  int lane = threadIdx.x & 31;
  if (g >= IC * NC) return;
  int i = g / NC, c = g - i * NC;
  const float* row = hm + i * CDP + c * DD;
  float vals[5];
  float s = 0.f, s2 = 0.f;
#pragma unroll
  for (int k = 0; k < 5; ++k) {
    int d = lane + 32 * k;
    float x = (d < DD) ? row[d] : 0.f;
    vals[k] = x;
    s += x;
    s2 += x * x;
  }
  s = warp_sum(s);
  s2 = warp_sum(s2);
  float mean = s * (1.f / DD);
  if (lane == 0) {
    meanA[c * IC + i] = mean;
    normA[c * IC + i] = sqrtf(fmaxf(s2 - DD * mean * mean, 0.f));
  }
#pragma unroll
  for (int k = 0; k < 5; ++k) {
    int d = lane + 32 * k;
    if (d < DD) hmT[(c * DD + d) * IC + i] = vals[k];
  }
}

// ---------------------------------------------------------------------------
// Routing v3: one block per query, 512 threads = 16 warps.
//   small:  warps 0..4 (c=w): tq update + sum/norm.
//   pass A: warps 0..14: c = w%5, d-chunk = w/5 (51 d's). lane owns 4 i's.
//           Partial num/mdv into num3/mdv3; no shfl.
//   i-pass: t<128: combine partials, a update, fast tanh/softmax, dsp.
//   pass B: thread per (c,d): dot over i (float4 hmT x float4 dsp).
//   squash: warps 0..4.
// ---------------------------------------------------------------------------
__global__ __launch_bounds__(512) void routing_kernel(
    const float* __restrict__ hmT, const float* __restrict__ meanA,
    const float* __restrict__ normA, const float* __restrict__ hq,
    float* __restrict__ out) {
  __shared__ __align__(16) float tq_s[NC * DP];
  __shared__ __align__(16) float v_s[NC * DP];
  __shared__ __align__(16) float hv_s[NC * DP];
  __shared__ __align__(16) float num3_s[NCHUNK * NC * IC];
  __shared__ __align__(16) float mdv3_s[NCHUNK * NC * IC];
  __shared__ __align__(16) float a_s[NC * IC];
  __shared__ __align__(16) float p_s[NC * IC];
  __shared__ __align__(16) float dsp_s[NC * IC];
  __shared__ __align__(16) float norm_sm[NC * IC];
  __shared__ __align__(16) float mean_sm[NC * IC];
  __shared__ float rnq[NC], stq[NC];

  const int q = blockIdx.x;
  const int t = threadIdx.x;
  const int w = t >> 5, lane = t & 31;

  for (int j = t; j < NC * DP; j += 512) {
    int c = j / DP, d = j - c * DP;
    tq_s[j] = (d < DD) ? hq[q * CDP + c * DD + d] : 0.f;
    v_s[j] = 0.f;
  }
  for (int j = t; j < NC * IC; j += 512) {
    a_s[j] = 0.f;
    p_s[j] = 0.f;
    norm_sm[j] = normA[j];
    mean_sm[j] = meanA[j];
  }
  __syncthreads();

  for (int r = 0; r < 3; ++r) {
    // ---- tq update + sum/norm per capsule (warps 0..4) ----
    if (w < NC) {
      const int c = w;
      float s = 0.f, s2 = 0.f;
      for (int d = lane; d < DD; d += 32) {
        float x = tq_s[c * DP + d];
        if (r > 0) {
          x = (x + v_s[c * DP + d]) * 0.5f;
          tq_s[c * DP + d] = x;
        }
        s += x;
        s2 += x * x;
      }
      s = warp_sum(s);
      s2 = warp_sum(s2);
      if (lane == 0) {
        float mean = s * (1.f / DD);
        rnq[c] = sqrtf(fmaxf(s2 - DD * mean * mean, 0.f));
        stq[c] = s;
      }
    }
    __syncthreads();

    // ---- pass A: 15 warps, partial num + mdv dots ----
    if (w < NC * NCHUNK) {
      const int c = w % NC;
      const int ch = w / NC;
      const int d0 = ch * DCH, d1 = d0 + DCH;
      const float* base = hmT + c * DD * IC + 4 * lane;
      const float* tqc = tq_s + c * DP;
      const float* vc = v_s + c * DP;
      float4 an = {0.f, 0.f, 0.f, 0.f};
      float4 av = {0.f, 0.f, 0.f, 0.f};
#pragma unroll 3
      for (int d = d0; d < d1; ++d) {
        float4 h = *(const float4*)(base + d * IC);
        float td = tqc[d], vd = vc[d];
        an.x += h.x * td; an.y += h.y * td; an.z += h.z * td; an.w += h.w * td;
        av.x += h.x * vd; av.y += h.y * vd; av.z += h.z * vd; av.w += h.w * vd;
      }
      const int o = ch * (NC * IC) + c * IC + 4 * lane;
      *(float4*)(num3_s + o) = an;
      *(float4*)(mdv3_s + o) = av;
    }
    __syncthreads();

    // ---- i-pass (t < 128): combine, a update, p, softmax, dsp ----
    if (t < IC) {
      float a[NC], p[NC];
      float amax = -1e30f;
#pragma unroll
      for (int c = 0; c < NC; ++c) {
        int o = c * IC + t;
        float num = num3_s[o] + num3_s[NC * IC + o] + num3_s[2 * NC * IC + o]
                    - mean_sm[o] * stq[c];
        float mdv = mdv3_s[o] + mdv3_s[NC * IC + o] + mdv3_s[2 * NC * IC + o];
        float po = p_s[o];
        float av = a_s[o] + po * mdv;
        a_s[o] = av;
        a[c] = av;
        float den = norm_sm[o] * rnq[c] + EPSF;
        float x = __fdividef(num, den);          // in [-1, 1]
        float e2 = __expf(2.f * x);
        p[c] = __fdividef(e2 - 1.f, e2 + 1.f);   // tanh(x)
        p_s[o] = p[c];
        amax = fmaxf(amax, av);
      }
      float es = 0.f, e[NC];
#pragma unroll
      for (int c = 0; c < NC; ++c) {
        e[c] = __expf(a[c] - amax);
        es += e[c];
      }
      float inv = __fdividef(1.f, es);
#pragma unroll
      for (int c = 0; c < NC; ++c) dsp_s[c * IC + t] = e[c] * inv + p[c];
    }
    __syncthreads();

    // ---- pass B: hv[c][d] = dot_i(hmT[c][d][:], dsp[c][:]) ----
    for (int j = t; j < CD; j += 512) {
      const int c = j / DD;
      const int d = j - c * DD;
      const float4* hr = (const float4*)(hmT + (c * DD + d) * IC);
      const float4* dp = (const float4*)(dsp_s + c * IC);
      float s0 = 0.f, s1 = 0.f, s2 = 0.f, s3 = 0.f;
#pragma unroll 8
      for (int k = 0; k < IC / 4; ++k) {
        float4 h = hr[k];
        float4 g = dp[k];
        s0 += h.x * g.x;
        s1 += h.y * g.y;
        s2 += h.z * g.z;
        s3 += h.w * g.w;
      }
      hv_s[c * DP + d] = (s0 + s1) + (s2 + s3);
    }
    __syncthreads();

    // ---- squash (warps 0..4) ----
    if (w < NC) {
      const int c = w;
      float s2 = 0.f;
      for (int d = lane; d < DD; d += 32) {
        float x = hv_s[c * DP + d];
        s2 += x * x;
      }
      s2 = warp_sum(s2);
      float sc = s2 / ((1.f + s2) * sqrtf(s2 + EPSF));
      if (r < 2) {
        for (int d = lane; d < DD; d += 32)
          v_s[c * DP + d] = hv_s[c * DP + d] * sc;
      } else {
        for (int d = lane; d < DD; d += 32)
          out[q * CD + c * DD + d] = hv_s[c * DP + d] * sc;
      }
    }
    __syncthreads();
  }
}

// ---------------------------------------------------------------------------
extern "C" void kernel_launch(void* const* d_in, const int* in_sizes, int n_in,
                              void* d_out, int out_size) {
  const float *m = nullptr, *q = nullptr, *W = nullptr, *b = nullptr;
  for (int i = 0; i < n_in; ++i) {
    switch (in_sizes[i]) {
      case IC * KD: m = (const float*)d_in[i]; break;
      case NQV * KD: q = (const float*)d_in[i]; break;
      case KD * CD: W = (const float*)d_in[i]; break;
      case CD: b = (const float*)d_in[i]; break;
      default: break;
    }
  }
  float* out = (float*)d_out;

  void *p_hm, *p_hq, *p_hmT, *p_mean, *p_norm, *p_wp;
  cudaGetSymbolAddress(&p_hm, g_hm);
  cudaGetSymbolAddress(&p_hq, g_hq);
  cudaGetSymbolAddress(&p_hmT, g_hmT);
  cudaGetSymbolAddress(&p_mean, g_mean);
  cudaGetSymbolAddress(&p_norm, g_norm);
  cudaGetSymbolAddress(&p_wp, g_Wp);

  wpad_kernel<<<(KD * CDP + 255) / 256, 256>>>(W, (float*)p_wp);

  dim3 gg(CDP / BN, (IC + NQV) / BM);  // (12, 12)
  gemm_kernel<<<gg, 256>>>(m, q, (const float*)p_wp, b, (float*)p_hm,
                           (float*)p_hq);

  stats_kernel<<<(IC * NC + 7) / 8, 256>>>((const float*)p_hm, (float*)p_hmT,
                                           (float*)p_mean, (float*)p_norm);

  routing_kernel<<<NQV, 512>>>((const float*)p_hmT, (const float*)p_mean,
                               (const float*)p_norm, (const float*)p_hq, out);
}

// round 4
// speedup vs baseline: 1.4936x; 1.4936x over previous
#include <cuda_runtime.h>
#include <cuda_fp16.h>
#include <math.h>

#define IC 128
#define NC 5
#define DD 153
#define DP 160      // padded capsule dim
#define CD 765
#define CDP 768     // padded row stride for GEMM outputs / Wp
#define ROWP 800    // NC*DP
#define KD 768
#define NQV 256
#define EPSF 1e-8f
#define NCHUNK 3
#define DCH 51      // DD / NCHUNK
#define GQ 2        // queries per routing block

__device__ __align__(16) float g_hm[IC * CDP];        // hat_m fp32 (GEMM out)
__device__ __align__(16) float g_hq[NQV * CDP];       // hat_q fp32
__device__ __align__(16) __half g_hmTh[NC * DD * IC]; // [c][d][i] fp16
__device__ __align__(16) __half g_hmPh[IC * ROWP];    // [i][c][dp] fp16, pads 0
__device__ __align__(16) float g_mean[NC * IC];       // [c][i]
__device__ __align__(16) float g_norm[NC * IC];       // [c][i]
__device__ __align__(16) float g_Wp[KD * CDP];        // zero-padded W

__device__ __forceinline__ float warp_sum(float v) {
#pragma unroll
  for (int o = 16; o; o >>= 1) v += __shfl_xor_sync(0xffffffffu, v, o);
  return v;
}

// ---------------------------------------------------------------------------
__global__ __launch_bounds__(256) void wpad_kernel(const float* __restrict__ W,
                                                   float* __restrict__ Wp) {
  int idx = blockIdx.x * 256 + threadIdx.x;
  if (idx < KD * CDP) {
    int k = idx / CDP, c = idx - k * CDP;
    Wp[idx] = (c < CD) ? W[k * CD + c] : 0.f;
  }
}

// ---------------------------------------------------------------------------
// Fused GEMM: rows 0..127 = m, 128..383 = q.  out = A @ Wp + b
// ---------------------------------------------------------------------------
#define BM 32
#define BN 64
#define BK 32

__global__ __launch_bounds__(256) void gemm_kernel(
    const float* __restrict__ Am, const float* __restrict__ Aq,
    const float* __restrict__ Wp, const float* __restrict__ bias,
    float* __restrict__ Om, float* __restrict__ Oq) {
  __shared__ float As[BK][BM + 1];
  __shared__ float Bs[BK][BN];
  const int t = threadIdx.x;
  const int row0 = blockIdx.y * BM;
  const int c0 = blockIdx.x * BN;

  const float* A;
  float* O;
  if (row0 < IC) { A = Am + row0 * KD; O = Om + row0 * CDP; }
  else           { A = Aq + (row0 - IC) * KD; O = Oq + (row0 - IC) * CDP; }

  const int ar = t >> 3, akc = (t & 7) << 2;
  const int br = t >> 4, bc = (t & 15) << 2;
  const int ty = t >> 4, tx = t & 15;

  float acc[2][4] = {};

  for (int k0 = 0; k0 < KD; k0 += BK) {
    float4 av = *(const float4*)(A + ar * KD + k0 + akc);
    As[akc + 0][ar] = av.x;
    As[akc + 1][ar] = av.y;
    As[akc + 2][ar] = av.z;
    As[akc + 3][ar] = av.w;
    *(float4*)&Bs[br][bc]      = *(const float4*)(Wp + (k0 + br) * CDP + c0 + bc);
    *(float4*)&Bs[br + 16][bc] = *(const float4*)(Wp + (k0 + br + 16) * CDP + c0 + bc);
    __syncthreads();
#pragma unroll
    for (int kk = 0; kk < BK; ++kk) {
      float a0 = As[kk][ty];
      float a1 = As[kk][ty + 16];
      float4 b = *(const float4*)&Bs[kk][tx << 2];
      acc[0][0] += a0 * b.x; acc[0][1] += a0 * b.y;
      acc[0][2] += a0 * b.z; acc[0][3] += a0 * b.w;
      acc[1][0] += a1 * b.x; acc[1][1] += a1 * b.y;
      acc[1][2] += a1 * b.z; acc[1][3] += a1 * b.w;
    }
    __syncthreads();
  }

#pragma unroll
  for (int rr = 0; rr < 2; ++rr) {
    int lr = ty + rr * 16;
#pragma unroll
    for (int j = 0; j < 4; ++j) {
      int c = c0 + (tx << 2) + j;
      if (c < CD) O[lr * CDP + c] = acc[rr][j] + bias[c];
    }
  }
}

// ---------------------------------------------------------------------------
// Stats: per (i,c) mean + centered norm; build hmPh [i][c][dp] fp16.
// One warp per (i,c). Coalesced contiguous stores.
// ---------------------------------------------------------------------------
__global__ __launch_bounds__(256) void stats_kernel(
    const float* __restrict__ hm, __half* __restrict__ hmPh,
    float* __restrict__ meanA, float* __restrict__ normA) {
  int g = blockIdx.x * 8 + (threadIdx.x >> 5);
  int lane = threadIdx.x & 31;
  if (g >= IC * NC) return;
  int i = g / NC, c = g - i * NC;
  const float* row = hm + i * CDP + c * DD;
  float vals[5];
  float s = 0.f, s2 = 0.f;
#pragma unroll
  for (int k = 0; k < 5; ++k) {
    int d = lane + 32 * k;
    float x = (d < DD) ? row[d] : 0.f;
    vals[k] = x;
    s += x;
    s2 += x * x;
  }
  s = warp_sum(s);
  s2 = warp_sum(s2);
  float mean = s * (1.f / DD);
  if (lane == 0) {
    meanA[c * IC + i] = mean;
    normA[c * IC + i] = sqrtf(fmaxf(s2 - DD * mean * mean, 0.f));
  }
#pragma unroll
  for (int k = 0; k < 5; ++k) {
    int d = lane + 32 * k;
    hmPh[i * ROWP + c * DP + d] = __float2half(vals[k]);
  }
}

// ---------------------------------------------------------------------------
// Transpose: build hmTh [c][d][i] fp16 from hm [i][c*DD+d] via smem tile.
// Grid (5 db, 4 ib, 5 c), block 32x8.
// ---------------------------------------------------------------------------
__global__ __launch_bounds__(256) void transT_kernel(
    const float* __restrict__ hm, __half* __restrict__ hmTh) {
  __shared__ float sm[32][33];
  const int c = blockIdx.z;
  const int i0 = blockIdx.y * 32;
  const int d0 = blockIdx.x * 32;
  const int tx = threadIdx.x, ty = threadIdx.y;
#pragma unroll
  for (int k = 0; k < 4; ++k) {
    int i = i0 + ty + 8 * k;
    int d = d0 + tx;
    sm[tx][ty + 8 * k] = (d < DD) ? hm[i * CDP + c * DD + d] : 0.f;
  }
  __syncthreads();
#pragma unroll
  for (int k = 0; k < 4; ++k) {
    int d = d0 + ty + 8 * k;
    if (d < DD)
      hmTh[(c * DD + d) * IC + i0 + tx] = __float2half(sm[ty + 8 * k][tx]);
  }
}

// ---------------------------------------------------------------------------
// Routing v4: one block per 2 queries, 512 threads = 16 warps, fp16 hat_m.
// dyn smem layout (floats):
//   tv   [GQ][NC*DP] float2 (tq=.x, v=.y)      : 3200
//   hv   [GQ][NC*DP]                            : 1600
//   num3 [GQ][NCHUNK][NC*IC]                    : 3840
//   mdv3 [GQ][NCHUNK][NC*IC]                    : 3840
//   a    [GQ][NC*IC]                            : 1280
//   p    [GQ][NC*IC]                            : 1280
//   dsp  [GQ][NC*IC]                            : 1280
//   rnq  [GQ][NC], stq [GQ][NC]                 : 20
// ---------------------------------------------------------------------------
#define SMF_TV 0
#define SMF_HV (SMF_TV + GQ * NC * DP * 2)
#define SMF_NUM (SMF_HV + GQ * NC * DP)
#define SMF_MDV (SMF_NUM + GQ * NCHUNK * NC * IC)
#define SMF_A (SMF_MDV + GQ * NCHUNK * NC * IC)
#define SMF_P (SMF_A + GQ * NC * IC)
#define SMF_DSP (SMF_P + GQ * NC * IC)
#define SMF_RNQ (SMF_DSP + GQ * NC * IC)
#define SMF_STQ (SMF_RNQ + GQ * NC)
#define SMF_TOTAL (SMF_STQ + GQ * NC)

__global__ __launch_bounds__(512) void routing_kernel(
    const __half* __restrict__ hmTh, const __half* __restrict__ hmPh,
    const float* __restrict__ meanA, const float* __restrict__ normA,
    const float* __restrict__ hq, float* __restrict__ out) {
  extern __shared__ float smem[];
  float2* tv = (float2*)(smem + SMF_TV);  // [qq*800 + c*DP + d]
  float* hv = smem + SMF_HV;
  float* num3 = smem + SMF_NUM;
  float* mdv3 = smem + SMF_MDV;
  float* a_s = smem + SMF_A;
  float* p_s = smem + SMF_P;
  float* dsp_s = smem + SMF_DSP;
  float* rnq = smem + SMF_RNQ;
  float* stq = smem + SMF_STQ;

  const int q0 = blockIdx.x * GQ;
  const int t = threadIdx.x;
  const int w = t >> 5, lane = t & 31;

  for (int j = t; j < GQ * NC * DP; j += 512) {
    int qq = j / (NC * DP);
    int rem = j - qq * NC * DP;
    int c = rem / DP, d = rem - c * DP;
    float x = (d < DD) ? hq[(q0 + qq) * CDP + c * DD + d] : 0.f;
    tv[j] = make_float2(x, 0.f);
  }
  for (int j = t; j < GQ * NC * IC; j += 512) {
    a_s[j] = 0.f;
    p_s[j] = 0.f;
  }
  __syncthreads();

  for (int r = 0; r < 3; ++r) {
    // ---- small pass: tq update + sum/norm (warps 0..9: qq=w/5, c=w%5) ----
    if (w < GQ * NC) {
      const int qq = w / NC, c = w - qq * NC;
      float2* tvc = tv + qq * (NC * DP) + c * DP;
      float s = 0.f, s2 = 0.f;
      for (int d = lane; d < DD; d += 32) {
        float2 xv = tvc[d];
        float x = xv.x;
        if (r > 0) {
          x = (x + xv.y) * 0.5f;
          tvc[d].x = x;
        }
        s += x;
        s2 += x * x;
      }
      s = warp_sum(s);
      s2 = warp_sum(s2);
      if (lane == 0) {
        float mean = s * (1.f / DD);
        rnq[qq * NC + c] = sqrtf(fmaxf(s2 - DD * mean * mean, 0.f));
        stq[qq * NC + c] = s;
      }
    }
    __syncthreads();

    // ---- pass A: warps 0..14 (c=w%5, chunk=w/5); lane owns 4 i's ----
    if (w < NC * NCHUNK) {
      const int c = w % NC;
      const int ch = w / NC;
      const int d0 = ch * DCH, d1 = d0 + DCH;
      const uint2* base = (const uint2*)hmTh + c * DD * (IC / 4) + lane;
      const float2* tv0 = tv + c * DP;
      const float2* tv1 = tv + NC * DP + c * DP;
      float4 an0 = {0, 0, 0, 0}, av0 = {0, 0, 0, 0};
      float4 an1 = {0, 0, 0, 0}, av1 = {0, 0, 0, 0};
#pragma unroll 3
      for (int d = d0; d < d1; ++d) {
        uint2 raw = base[d * (IC / 4)];
        float2 f01 = __half22float2(*(__half2*)&raw.x);
        float2 f23 = __half22float2(*(__half2*)&raw.y);
        float2 t0 = tv0[d], t1 = tv1[d];
        an0.x += f01.x * t0.x; an0.y += f01.y * t0.x;
        an0.z += f23.x * t0.x; an0.w += f23.y * t0.x;
        av0.x += f01.x * t0.y; av0.y += f01.y * t0.y;
        av0.z += f23.x * t0.y; av0.w += f23.y * t0.y;
        an1.x += f01.x * t1.x; an1.y += f01.y * t1.x;
        an1.z += f23.x * t1.x; an1.w += f23.y * t1.x;
        av1.x += f01.x * t1.y; av1.y += f01.y * t1.y;
        av1.z += f23.x * t1.y; av1.w += f23.y * t1.y;
      }
      const int o = ch * (NC * IC) + c * IC + 4 * lane;
      *(float4*)(num3 + o) = an0;
      *(float4*)(mdv3 + o) = av0;
      *(float4*)(num3 + NCHUNK * NC * IC + o) = an1;
      *(float4*)(mdv3 + NCHUNK * NC * IC + o) = av1;
    }
    __syncthreads();

    // ---- i-pass (t < 256): qq = t>>7, i = t&127 ----
    if (t < GQ * IC) {
      const int qq = t >> 7, i = t & 127;
      const int qb = qq * NC * IC;
      const int q3 = qq * NCHUNK * NC * IC;
      float a[NC], p[NC];
      float amax = -1e30f;
#pragma unroll
      for (int c = 0; c < NC; ++c) {
        int o = c * IC + i;
        float num = num3[q3 + o] + num3[q3 + NC * IC + o] +
                    num3[q3 + 2 * NC * IC + o] -
                    __ldg(meanA + o) * stq[qq * NC + c];
        float mdv = mdv3[q3 + o] + mdv3[q3 + NC * IC + o] +
                    mdv3[q3 + 2 * NC * IC + o];
        float po = p_s[qb + o];
        float av = a_s[qb + o] + po * mdv;
        a_s[qb + o] = av;
        a[c] = av;
        float den = __ldg(normA + o) * rnq[qq * NC + c] + EPSF;
        float x = __fdividef(num, den);
        float e2 = __expf(2.f * x);
        p[c] = __fdividef(e2 - 1.f, e2 + 1.f);
        p_s[qb + o] = p[c];
        amax = fmaxf(amax, av);
      }
      float es = 0.f, e[NC];
#pragma unroll
      for (int c = 0; c < NC; ++c) {
        e[c] = __expf(a[c] - amax);
        es += e[c];
      }
      float inv = __fdividef(1.f, es);
#pragma unroll
      for (int c = 0; c < NC; ++c) dsp_s[qb + c * IC + i] = e[c] * inv + p[c];
    }
    __syncthreads();

    // ---- pass B: thread t < 400 owns (c, d-pair); loop over i, coalesced ----
    if (t < NC * DP / 2) {
      const int c = t / (DP / 2);
      const int d2 = t - c * (DP / 2);
      const __half2* hp = (const __half2*)hmPh + c * (DP / 2) + d2;
      const float* w0 = dsp_s + c * IC;
      const float* w1 = dsp_s + NC * IC + c * IC;
      float2 acc0 = {0, 0}, acc1 = {0, 0};
#pragma unroll 16
      for (int i = 0; i < IC; ++i) {
        float2 f = __half22float2(hp[i * (ROWP / 2)]);
        float g0 = w0[i], g1 = w1[i];
        acc0.x += f.x * g0; acc0.y += f.y * g0;
        acc1.x += f.x * g1; acc1.y += f.y * g1;
      }
      hv[c * DP + 2 * d2] = acc0.x;
      hv[c * DP + 2 * d2 + 1] = acc0.y;
      hv[NC * DP + c * DP + 2 * d2] = acc1.x;
      hv[NC * DP + c * DP + 2 * d2 + 1] = acc1.y;
    }
    __syncthreads();

    // ---- squash (warps 0..9) ----
    if (w < GQ * NC) {
      const int qq = w / NC, c = w - qq * NC;
      const float* hvc = hv + qq * NC * DP + c * DP;
      float s2 = 0.f;
      for (int d = lane; d < DD; d += 32) {
        float x = hvc[d];
        s2 += x * x;
      }
      s2 = warp_sum(s2);
      float sc = s2 / ((1.f + s2) * sqrtf(s2 + EPSF));
      if (r < 2) {
        float2* tvc = tv + qq * NC * DP + c * DP;
        for (int d = lane; d < DD; d += 32) tvc[d].y = hvc[d] * sc;
      } else {
        for (int d = lane; d < DD; d += 32)
          out[(q0 + qq) * CD + c * DD + d] = hvc[d] * sc;
      }
    }
    __syncthreads();
  }
}

// ---------------------------------------------------------------------------
extern "C" void kernel_launch(void* const* d_in, const int* in_sizes, int n_in,
                              void* d_out, int out_size) {
  const float *m = nullptr, *q = nullptr, *W = nullptr, *b = nullptr;
  for (int i = 0; i < n_in; ++i) {
    switch (in_sizes[i]) {
      case IC * KD: m = (const float*)d_in[i]; break;
      case NQV * KD: q = (const float*)d_in[i]; break;
      case KD * CD: W = (const float*)d_in[i]; break;
      case CD: b = (const float*)d_in[i]; break;
      default: break;
    }
  }
  float* out = (float*)d_out;

  void *p_hm, *p_hq, *p_hmTh, *p_hmPh, *p_mean, *p_norm, *p_wp;
  cudaGetSymbolAddress(&p_hm, g_hm);
  cudaGetSymbolAddress(&p_hq, g_hq);
  cudaGetSymbolAddress(&p_hmTh, g_hmTh);
  cudaGetSymbolAddress(&p_hmPh, g_hmPh);
  cudaGetSymbolAddress(&p_mean, g_mean);
  cudaGetSymbolAddress(&p_norm, g_norm);
  cudaGetSymbolAddress(&p_wp, g_Wp);

  static bool attr_set = false;
  if (!attr_set) {
    cudaFuncSetAttribute(routing_kernel,
                         cudaFuncAttributeMaxDynamicSharedMemorySize,
                         SMF_TOTAL * 4);
    attr_set = true;
  }

  wpad_kernel<<<(KD * CDP + 255) / 256, 256>>>(W, (float*)p_wp);

  dim3 gg(CDP / BN, (IC + NQV) / BM);
  gemm_kernel<<<gg, 256>>>(m, q, (const float*)p_wp, b, (float*)p_hm,
                           (float*)p_hq);

  stats_kernel<<<(IC * NC + 7) / 8, 256>>>((const float*)p_hm,
                                           (__half*)p_hmPh, (float*)p_mean,
                                           (float*)p_norm);
  dim3 tg(5, 4, 5);
  transT_kernel<<<tg, dim3(32, 8)>>>((const float*)p_hm, (__half*)p_hmTh);

  routing_kernel<<<NQV / GQ, 512, SMF_TOTAL * 4>>>(
      (const __half*)p_hmTh, (const __half*)p_hmPh, (const float*)p_mean,
      (const float*)p_norm, (const float*)p_hq, out);
}

// round 5
// speedup vs baseline: 1.7365x; 1.1626x over previous
#include <cuda_runtime.h>
#include <cuda_fp16.h>
#include <math.h>

#define IC 128
#define NC 5
#define DD 153
#define DP 160      // padded capsule dim
#define CD 765
#define CDP 768     // padded row stride for GEMM outputs / Wp
#define ROWP 800    // NC*DP
#define KD 768
#define NQV 256
#define EPSF 1e-8f
#define NCHUNK 3
#define DCH 51      // DD / NCHUNK
#define GQ 2        // queries per routing block

__device__ __align__(16) float g_hm[IC * CDP];        // hat_m fp32 (GEMM out)
__device__ __align__(16) float g_hq[NQV * CDP];       // hat_q fp32
__device__ __align__(16) __half g_hmTh[NC * DD * IC]; // [c][d][i] fp16
__device__ __align__(16) __half g_hmPh[IC * ROWP];    // [i][c][dp] fp16, pads 0
__device__ __align__(16) float g_mean[NC * IC];       // [c][i]
__device__ __align__(16) float g_norm[NC * IC];       // [c][i]
__device__ __align__(16) float g_Wp[KD * CDP];        // zero-padded W

__device__ __forceinline__ float warp_sum(float v) {
#pragma unroll
  for (int o = 16; o; o >>= 1) v += __shfl_xor_sync(0xffffffffu, v, o);
  return v;
}

// ---------------------------------------------------------------------------
__global__ __launch_bounds__(256) void wpad_kernel(const float* __restrict__ W,
                                                   float* __restrict__ Wp) {
  int idx = blockIdx.x * 256 + threadIdx.x;
  if (idx < KD * CDP) {
    int k = idx / CDP, c = idx - k * CDP;
    Wp[idx] = (c < CD) ? W[k * CD + c] : 0.f;
  }
}

// ---------------------------------------------------------------------------
// Fused GEMM: rows 0..127 = m, 128..383 = q.  out = A @ Wp + b
// ---------------------------------------------------------------------------
#define BM 32
#define BN 64
#define BK 32

__global__ __launch_bounds__(256) void gemm_kernel(
    const float* __restrict__ Am, const float* __restrict__ Aq,
    const float* __restrict__ Wp, const float* __restrict__ bias,
    float* __restrict__ Om, float* __restrict__ Oq) {
  __shared__ float As[BK][BM + 1];
  __shared__ float Bs[BK][BN];
  const int t = threadIdx.x;
  const int row0 = blockIdx.y * BM;
  const int c0 = blockIdx.x * BN;

  const float* A;
  float* O;
  if (row0 < IC) { A = Am + row0 * KD; O = Om + row0 * CDP; }
  else           { A = Aq + (row0 - IC) * KD; O = Oq + (row0 - IC) * CDP; }

  const int ar = t >> 3, akc = (t & 7) << 2;
  const int br = t >> 4, bc = (t & 15) << 2;
  const int ty = t >> 4, tx = t & 15;

  float acc[2][4] = {};

  for (int k0 = 0; k0 < KD; k0 += BK) {
    float4 av = *(const float4*)(A + ar * KD + k0 + akc);
    As[akc + 0][ar] = av.x;
    As[akc + 1][ar] = av.y;
    As[akc + 2][ar] = av.z;
    As[akc + 3][ar] = av.w;
    *(float4*)&Bs[br][bc]      = *(const float4*)(Wp + (k0 + br) * CDP + c0 + bc);
    *(float4*)&Bs[br + 16][bc] = *(const float4*)(Wp + (k0 + br + 16) * CDP + c0 + bc);
    __syncthreads();
#pragma unroll
    for (int kk = 0; kk < BK; ++kk) {
      float a0 = As[kk][ty];
      float a1 = As[kk][ty + 16];
      float4 b = *(const float4*)&Bs[kk][tx << 2];
      acc[0][0] += a0 * b.x; acc[0][1] += a0 * b.y;
      acc[0][2] += a0 * b.z; acc[0][3] += a0 * b.w;
      acc[1][0] += a1 * b.x; acc[1][1] += a1 * b.y;
      acc[1][2] += a1 * b.z; acc[1][3] += a1 * b.w;
    }
    __syncthreads();
  }

#pragma unroll
  for (int rr = 0; rr < 2; ++rr) {
    int lr = ty + rr * 16;
#pragma unroll
    for (int j = 0; j < 4; ++j) {
      int c = c0 + (tx << 2) + j;
      if (c < CD) O[lr * CDP + c] = acc[rr][j] + bias[c];
    }
  }
}

// ---------------------------------------------------------------------------
// Stats: per (i,c) mean + centered norm; build hmPh [i][c][dp] fp16.
// ---------------------------------------------------------------------------
__global__ __launch_bounds__(256) void stats_kernel(
    const float* __restrict__ hm, __half* __restrict__ hmPh,
    float* __restrict__ meanA, float* __restrict__ normA) {
  int g = blockIdx.x * 8 + (threadIdx.x >> 5);
  int lane = threadIdx.x & 31;
  if (g >= IC * NC) return;
  int i = g / NC, c = g - i * NC;
  const float* row = hm + i * CDP + c * DD;
  float vals[5];
  float s = 0.f, s2 = 0.f;
#pragma unroll
  for (int k = 0; k < 5; ++k) {
    int d = lane + 32 * k;
    float x = (d < DD) ? row[d] : 0.f;
    vals[k] = x;
    s += x;
    s2 += x * x;
  }
  s = warp_sum(s);
  s2 = warp_sum(s2);
  float mean = s * (1.f / DD);
  if (lane == 0) {
    meanA[c * IC + i] = mean;
    normA[c * IC + i] = sqrtf(fmaxf(s2 - DD * mean * mean, 0.f));
  }
#pragma unroll
  for (int k = 0; k < 5; ++k) {
    int d = lane + 32 * k;
    hmPh[i * ROWP + c * DP + d] = __float2half(vals[k]);
  }
}

// ---------------------------------------------------------------------------
// Transpose: build hmTh [c][d][i] fp16 from hm via smem tile.
// ---------------------------------------------------------------------------
__global__ __launch_bounds__(256) void transT_kernel(
    const float* __restrict__ hm, __half* __restrict__ hmTh) {
  __shared__ float sm[32][33];
  const int c = blockIdx.z;
  const int i0 = blockIdx.y * 32;
  const int d0 = blockIdx.x * 32;
  const int tx = threadIdx.x, ty = threadIdx.y;
#pragma unroll
  for (int k = 0; k < 4; ++k) {
    int i = i0 + ty + 8 * k;
    int d = d0 + tx;
    sm[tx][ty + 8 * k] = (d < DD) ? hm[i * CDP + c * DD + d] : 0.f;
  }
  __syncthreads();
#pragma unroll
  for (int k = 0; k < 4; ++k) {
    int d = d0 + ty + 8 * k;
    if (d < DD)
      hmTh[(c * DD + d) * IC + i0 + tx] = __float2half(sm[ty + 8 * k][tx]);
  }
}

// ---------------------------------------------------------------------------
// Routing v5: block per 2 queries, 512 threads. 4 phases / round:
//   A: num (+mdv if r>0), 15 warps (c,chunk), lane owns 4 i's.
//   I: per-(qq,i) a-update/p/softmax/dsp (round 0: dsp = 0.2+p, no exp).
//   B: hv dot over i; thread per (qq,c,d2), all 512 threads.
//   S: squash + (if r<2) tq update + next norms (fused small pass).
// ---------------------------------------------------------------------------
#define SMF_TV 0
#define SMF_HV (SMF_TV + GQ * NC * DP * 2)
#define SMF_NUM (SMF_HV + GQ * NC * DP)
#define SMF_MDV (SMF_NUM + GQ * NCHUNK * NC * IC)
#define SMF_A (SMF_MDV + GQ * NCHUNK * NC * IC)
#define SMF_P (SMF_A + GQ * NC * IC)
#define SMF_DSP (SMF_P + GQ * NC * IC)
#define SMF_RNQ (SMF_DSP + GQ * NC * IC)
#define SMF_STQ (SMF_RNQ + GQ * NC)
#define SMF_TOTAL (SMF_STQ + GQ * NC)

__global__ __launch_bounds__(512) void routing_kernel(
    const __half* __restrict__ hmTh, const __half* __restrict__ hmPh,
    const float* __restrict__ meanA, const float* __restrict__ normA,
    const float* __restrict__ hq, float* __restrict__ out) {
  extern __shared__ float smem[];
  float2* tv = (float2*)(smem + SMF_TV);  // .x = tq, .y = v
  float* hv = smem + SMF_HV;
  float* num3 = smem + SMF_NUM;
  float* mdv3 = smem + SMF_MDV;
  float* a_s = smem + SMF_A;
  float* p_s = smem + SMF_P;
  float* dsp_s = smem + SMF_DSP;
  float* rnq = smem + SMF_RNQ;
  float* stq = smem + SMF_STQ;

  const int q0 = blockIdx.x * GQ;
  const int t = threadIdx.x;
  const int w = t >> 5, lane = t & 31;

  for (int j = t; j < GQ * NC * DP; j += 512) {
    int qq = j / (NC * DP);
    int rem = j - qq * NC * DP;
    int c = rem / DP, d = rem - c * DP;
    float x = (d < DD) ? hq[(q0 + qq) * CDP + c * DD + d] : 0.f;
    tv[j] = make_float2(x, 0.f);
  }
  for (int j = t; j < GQ * NC * IC; j += 512) a_s[j] = 0.f;
  __syncthreads();

  // prologue: initial norms (warps 0..9: qq=w/5, c=w%5)
  if (w < GQ * NC) {
    const int qq = w / NC, c = w - qq * NC;
    const float2* tvc = tv + qq * (NC * DP) + c * DP;
    float s = 0.f, s2 = 0.f;
    for (int d = lane; d < DD; d += 32) {
      float x = tvc[d].x;
      s += x;
      s2 += x * x;
    }
    s = warp_sum(s);
    s2 = warp_sum(s2);
    if (lane == 0) {
      float mean = s * (1.f / DD);
      rnq[qq * NC + c] = sqrtf(fmaxf(s2 - DD * mean * mean, 0.f));
      stq[qq * NC + c] = s;
    }
  }
  __syncthreads();

  for (int r = 0; r < 3; ++r) {
    // ---- phase A ----
    if (w < NC * NCHUNK) {
      const int c = w % NC;
      const int ch = w / NC;
      const int d0 = ch * DCH, d1 = d0 + DCH;
      const uint2* base = (const uint2*)hmTh + c * DD * (IC / 4) + lane;
      const float2* tv0 = tv + c * DP;
      const float2* tv1 = tv + NC * DP + c * DP;
      const int o = ch * (NC * IC) + c * IC + 4 * lane;
      if (r == 0) {
        float4 an0 = {0, 0, 0, 0}, an1 = {0, 0, 0, 0};
#pragma unroll 3
        for (int d = d0; d < d1; ++d) {
          uint2 raw = base[d * (IC / 4)];
          float2 f01 = __half22float2(*(__half2*)&raw.x);
          float2 f23 = __half22float2(*(__half2*)&raw.y);
          float t0 = tv0[d].x, t1 = tv1[d].x;
          an0.x += f01.x * t0; an0.y += f01.y * t0;
          an0.z += f23.x * t0; an0.w += f23.y * t0;
          an1.x += f01.x * t1; an1.y += f01.y * t1;
          an1.z += f23.x * t1; an1.w += f23.y * t1;
        }
        *(float4*)(num3 + o) = an0;
        *(float4*)(num3 + NCHUNK * NC * IC + o) = an1;
      } else {
        float4 an0 = {0, 0, 0, 0}, av0 = {0, 0, 0, 0};
        float4 an1 = {0, 0, 0, 0}, av1 = {0, 0, 0, 0};
#pragma unroll 3
        for (int d = d0; d < d1; ++d) {
          uint2 raw = base[d * (IC / 4)];
          float2 f01 = __half22float2(*(__half2*)&raw.x);
          float2 f23 = __half22float2(*(__half2*)&raw.y);
          float2 t0 = tv0[d], t1 = tv1[d];
          an0.x += f01.x * t0.x; an0.y += f01.y * t0.x;
          an0.z += f23.x * t0.x; an0.w += f23.y * t0.x;
          av0.x += f01.x * t0.y; av0.y += f01.y * t0.y;
          av0.z += f23.x * t0.y; av0.w += f23.y * t0.y;
          an1.x += f01.x * t1.x; an1.y += f01.y * t1.x;
          an1.z += f23.x * t1.x; an1.w += f23.y * t1.x;
          av1.x += f01.x * t1.y; av1.y += f01.y * t1.y;
          av1.z += f23.x * t1.y; av1.w += f23.y * t1.y;
        }
        *(float4*)(num3 + o) = an0;
        *(float4*)(mdv3 + o) = av0;
        *(float4*)(num3 + NCHUNK * NC * IC + o) = an1;
        *(float4*)(mdv3 + NCHUNK * NC * IC + o) = av1;
      }
    }
    __syncthreads();

    // ---- phase I ----
    if (t < GQ * IC) {
      const int qq = t >> 7, i = t & 127;
      const int qb = qq * NC * IC;
      const int q3 = qq * NCHUNK * NC * IC;
      float p[NC];
      if (r == 0) {
#pragma unroll
        for (int c = 0; c < NC; ++c) {
          int o = c * IC + i;
          float num = num3[q3 + o] + num3[q3 + NC * IC + o] +
                      num3[q3 + 2 * NC * IC + o] -
                      __ldg(meanA + o) * stq[qq * NC + c];
          float den = __ldg(normA + o) * rnq[qq * NC + c] + EPSF;
          float x = __fdividef(num, den);
          float e2 = __expf(2.f * x);
          p[c] = __fdividef(e2 - 1.f, e2 + 1.f);
          p_s[qb + o] = p[c];
          dsp_s[qb + o] = 0.2f + p[c];  // softmax of zeros
        }
      } else {
        float a[NC];
        float amax = -1e30f;
#pragma unroll
        for (int c = 0; c < NC; ++c) {
          int o = c * IC + i;
          float num = num3[q3 + o] + num3[q3 + NC * IC + o] +
                      num3[q3 + 2 * NC * IC + o] -
                      __ldg(meanA + o) * stq[qq * NC + c];
          float mdv = mdv3[q3 + o] + mdv3[q3 + NC * IC + o] +
                      mdv3[q3 + 2 * NC * IC + o];
          float po = p_s[qb + o];
          float av = a_s[qb + o] + po * mdv;
          a_s[qb + o] = av;
          a[c] = av;
          float den = __ldg(normA + o) * rnq[qq * NC + c] + EPSF;
          float x = __fdividef(num, den);
          float e2 = __expf(2.f * x);
          p[c] = __fdividef(e2 - 1.f, e2 + 1.f);
          p_s[qb + o] = p[c];
          amax = fmaxf(amax, av);
        }
        float es = 0.f, e[NC];
#pragma unroll
        for (int c = 0; c < NC; ++c) {
          e[c] = __expf(a[c] - amax);
          es += e[c];
        }
        float inv = __fdividef(1.f, es);
#pragma unroll
        for (int c = 0; c < NC; ++c) dsp_s[qb + c * IC + i] = e[c] * inv + p[c];
      }
    }
    __syncthreads();

    // ---- phase B: 800 units (qq,c,d2) over 512 threads ----
    for (int j = t; j < GQ * NC * (DP / 2); j += 512) {
      const int qq = j / (NC * (DP / 2));
      const int rem = j - qq * NC * (DP / 2);
      const int c = rem / (DP / 2);
      const int d2 = rem - c * (DP / 2);
      const __half2* hp = (const __half2*)hmPh + c * (DP / 2) + d2;
      const float* wq = dsp_s + qq * NC * IC + c * IC;
      float ax = 0.f, ay = 0.f;
#pragma unroll 16
      for (int i = 0; i < IC; ++i) {
        float2 f = __half22float2(hp[i * (ROWP / 2)]);
        float g = wq[i];
        ax += f.x * g;
        ay += f.y * g;
      }
      hv[qq * NC * DP + c * DP + 2 * d2] = ax;
      hv[qq * NC * DP + c * DP + 2 * d2 + 1] = ay;
    }
    __syncthreads();

    // ---- phase S: squash + next tq + next norms ----
    if (w < GQ * NC) {
      const int qq = w / NC, c = w - qq * NC;
      const float* hvc = hv + qq * NC * DP + c * DP;
      float s2 = 0.f;
      for (int d = lane; d < DD; d += 32) {
        float x = hvc[d];
        s2 += x * x;
      }
      s2 = warp_sum(s2);
      float sc = s2 / ((1.f + s2) * sqrtf(s2 + EPSF));
      if (r < 2) {
        float2* tvc = tv + qq * NC * DP + c * DP;
        float s = 0.f, sq = 0.f;
        for (int d = lane; d < DD; d += 32) {
          float vd = hvc[d] * sc;
          float x = (tvc[d].x + vd) * 0.5f;
          tvc[d] = make_float2(x, vd);
          s += x;
          sq += x * x;
        }
        s = warp_sum(s);
        sq = warp_sum(sq);
        if (lane == 0) {
          float mean = s * (1.f / DD);
          rnq[qq * NC + c] = sqrtf(fmaxf(sq - DD * mean * mean, 0.f));
          stq[qq * NC + c] = s;
        }
      } else {
        for (int d = lane; d < DD; d += 32)
          out[(q0 + qq) * CD + c * DD + d] = hvc[d] * sc;
      }
    }
    __syncthreads();
  }
}

// ---------------------------------------------------------------------------
extern "C" void kernel_launch(void* const* d_in, const int* in_sizes, int n_in,
                              void* d_out, int out_size) {
  const float *m = nullptr, *q = nullptr, *W = nullptr, *b = nullptr;
  for (int i = 0; i < n_in; ++i) {
    switch (in_sizes[i]) {
      case IC * KD: m = (const float*)d_in[i]; break;
      case NQV * KD: q = (const float*)d_in[i]; break;
      case KD * CD: W = (const float*)d_in[i]; break;
      case CD: b = (const float*)d_in[i]; break;
      default: break;
    }
  }
  float* out = (float*)d_out;

  void *p_hm, *p_hq, *p_hmTh, *p_hmPh, *p_mean, *p_norm, *p_wp;
  cudaGetSymbolAddress(&p_hm, g_hm);
  cudaGetSymbolAddress(&p_hq, g_hq);
  cudaGetSymbolAddress(&p_hmTh, g_hmTh);
  cudaGetSymbolAddress(&p_hmPh, g_hmPh);
  cudaGetSymbolAddress(&p_mean, g_mean);
  cudaGetSymbolAddress(&p_norm, g_norm);
  cudaGetSymbolAddress(&p_wp, g_Wp);

  static bool attr_set = false;
  if (!attr_set) {
    cudaFuncSetAttribute(routing_kernel,
                         cudaFuncAttributeMaxDynamicSharedMemorySize,
                         SMF_TOTAL * 4);
    attr_set = true;
  }

  wpad_kernel<<<(KD * CDP + 255) / 256, 256>>>(W, (float*)p_wp);

  dim3 gg(CDP / BN, (IC + NQV) / BM);
  gemm_kernel<<<gg, 256>>>(m, q, (const float*)p_wp, b, (float*)p_hm,
                           (float*)p_hq);

  stats_kernel<<<(IC * NC + 7) / 8, 256>>>((const float*)p_hm,
                                           (__half*)p_hmPh, (float*)p_mean,
                                           (float*)p_norm);
  dim3 tg(5, 4, 5);
  transT_kernel<<<tg, dim3(32, 8)>>>((const float*)p_hm, (__half*)p_hmTh);

  routing_kernel<<<NQV / GQ, 512, SMF_TOTAL * 4>>>(
      (const __half*)p_hmTh, (const __half*)p_hmPh, (const float*)p_mean,
      (const float*)p_norm, (const float*)p_hq, out);
}

// round 6
// speedup vs baseline: 1.8660x; 1.0746x over previous
#include <cuda_runtime.h>
#include <cuda_fp16.h>
#include <math.h>

#define IC 128
#define NC 5
#define DD 153
#define DP 160      // padded capsule dim
#define CD 765
#define CDP 768     // padded row stride for GEMM outputs / Wp
#define ROWP 800    // NC*DP
#define KD 768
#define NQV 256
#define EPSF 1e-8f
#define NCHUNK 3
#define DCH 51      // DD / NCHUNK
#define GQ 2        // queries per routing block

__device__ __align__(16) float g_hm[IC * CDP];        // hat_m fp32 (GEMM out)
__device__ __align__(16) float g_hq[NQV * CDP];       // hat_q fp32
__device__ __align__(16) __half g_hmTh[NC * DD * IC]; // [c][d][i] fp16
__device__ __align__(16) __half g_hmPh[IC * ROWP];    // [i][c][dp] fp16, pads 0
__device__ __align__(16) float g_mean[NC * IC];       // [c][i]
__device__ __align__(16) float g_norm[NC * IC];       // [c][i]
__device__ __align__(16) float g_Wp[KD * CDP];        // zero-padded W

__device__ __forceinline__ float warp_sum(float v) {
#pragma unroll
  for (int o = 16; o; o >>= 1) v += __shfl_xor_sync(0xffffffffu, v, o);
  return v;
}

// ---------------------------------------------------------------------------
__global__ __launch_bounds__(256) void wpad_kernel(const float* __restrict__ W,
                                                   float* __restrict__ Wp) {
  int idx = blockIdx.x * 256 + threadIdx.x;
  if (idx < KD * CDP) {
    int k = idx / CDP, c = idx - k * CDP;
    Wp[idx] = (c < CD) ? W[k * CD + c] : 0.f;
  }
}

// ---------------------------------------------------------------------------
// Fused GEMM: rows 0..127 = m, 128..383 = q.  out = A @ Wp + b
// ---------------------------------------------------------------------------
#define BM 32
#define BN 64
#define BK 32

__global__ __launch_bounds__(256) void gemm_kernel(
    const float* __restrict__ Am, const float* __restrict__ Aq,
    const float* __restrict__ Wp, const float* __restrict__ bias,
    float* __restrict__ Om, float* __restrict__ Oq) {
  __shared__ float As[BK][BM + 1];
  __shared__ float Bs[BK][BN];
  const int t = threadIdx.x;
  const int row0 = blockIdx.y * BM;
  const int c0 = blockIdx.x * BN;

  const float* A;
  float* O;
  if (row0 < IC) { A = Am + row0 * KD; O = Om + row0 * CDP; }
  else           { A = Aq + (row0 - IC) * KD; O = Oq + (row0 - IC) * CDP; }

  const int ar = t >> 3, akc = (t & 7) << 2;
  const int br = t >> 4, bc = (t & 15) << 2;
  const int ty = t >> 4, tx = t & 15;

  float acc[2][4] = {};

  for (int k0 = 0; k0 < KD; k0 += BK) {
    float4 av = *(const float4*)(A + ar * KD + k0 + akc);
    As[akc + 0][ar] = av.x;
    As[akc + 1][ar] = av.y;
    As[akc + 2][ar] = av.z;
    As[akc + 3][ar] = av.w;
    *(float4*)&Bs[br][bc]      = *(const float4*)(Wp + (k0 + br) * CDP + c0 + bc);
    *(float4*)&Bs[br + 16][bc] = *(const float4*)(Wp + (k0 + br + 16) * CDP + c0 + bc);
    __syncthreads();
#pragma unroll
    for (int kk = 0; kk < BK; ++kk) {
      float a0 = As[kk][ty];
      float a1 = As[kk][ty + 16];
      float4 b = *(const float4*)&Bs[kk][tx << 2];
      acc[0][0] += a0 * b.x; acc[0][1] += a0 * b.y;
      acc[0][2] += a0 * b.z; acc[0][3] += a0 * b.w;
      acc[1][0] += a1 * b.x; acc[1][1] += a1 * b.y;
      acc[1][2] += a1 * b.z; acc[1][3] += a1 * b.w;
    }
    __syncthreads();
  }

#pragma unroll
  for (int rr = 0; rr < 2; ++rr) {
    int lr = ty + rr * 16;
#pragma unroll
    for (int j = 0; j < 4; ++j) {
      int c = c0 + (tx << 2) + j;
      if (c < CD) O[lr * CDP + c] = acc[rr][j] + bias[c];
    }
  }
}

// ---------------------------------------------------------------------------
// Prep (merged): blocks 0..79 = stats (mean/norm + hmPh fp16),
//                blocks 80..179 = transpose into hmTh fp16.
// ---------------------------------------------------------------------------
__global__ __launch_bounds__(256) void prep_kernel(
    const float* __restrict__ hm, __half* __restrict__ hmPh,
    __half* __restrict__ hmTh, float* __restrict__ meanA,
    float* __restrict__ normA) {
  const int t = threadIdx.x;
  if (blockIdx.x < 80) {
    // ---- stats: one warp per (i,c) ----
    int g = blockIdx.x * 8 + (t >> 5);
    int lane = t & 31;
    int i = g / NC, c = g - i * NC;
    const float* row = hm + i * CDP + c * DD;
    float vals[5];
    float s = 0.f, s2 = 0.f;
#pragma unroll
    for (int k = 0; k < 5; ++k) {
      int d = lane + 32 * k;
      float x = (d < DD) ? row[d] : 0.f;
      vals[k] = x;
      s += x;
      s2 += x * x;
    }
    s = warp_sum(s);
    s2 = warp_sum(s2);
    float mean = s * (1.f / DD);
    if (lane == 0) {
      meanA[c * IC + i] = mean;
      normA[c * IC + i] = sqrtf(fmaxf(s2 - DD * mean * mean, 0.f));
    }
#pragma unroll
    for (int k = 0; k < 5; ++k) {
      int d = lane + 32 * k;
      hmPh[i * ROWP + c * DP + d] = __float2half(vals[k]);
    }
  } else {
    // ---- transpose tile: bx -> (c, i0, d0) ----
    __shared__ float sm[32][33];
    int bx = blockIdx.x - 80;
    int c = bx / 20;
    int rem = bx - c * 20;
    int i0 = (rem / 5) * 32;
    int d0 = (rem % 5) * 32;
    int tx = t & 31, ty = t >> 5;
#pragma unroll
    for (int k = 0; k < 4; ++k) {
      int i = i0 + ty + 8 * k;
      int d = d0 + tx;
      sm[tx][ty + 8 * k] = (d < DD) ? hm[i * CDP + c * DD + d] : 0.f;
    }
    __syncthreads();
#pragma unroll
    for (int k = 0; k < 4; ++k) {
      int d = d0 + ty + 8 * k;
      if (d < DD)
        hmTh[(c * DD + d) * IC + i0 + tx] = __float2half(sm[ty + 8 * k][tx]);
    }
  }
}

// ---------------------------------------------------------------------------
// Routing v6: block per 2 queries, 1024 threads = 32 warps.
//   A: 30 warps: w = qq*15 + ch*5 + c; each warp one query, 51 d's,
//      lane owns 4 i's (uint2 = 4 fp16). num (+mdv if r>0).
//   I: t < 256: per-(qq,i) a-update/p/softmax/dsp.
//   B: t < 800: thread per (qq,c,d2), single pass over i.
//   S: warps 0..9: squash + tq update + next norms.
// ---------------------------------------------------------------------------
#define SMF_TV 0
#define SMF_HV (SMF_TV + GQ * NC * DP * 2)
#define SMF_NUM (SMF_HV + GQ * NC * DP)
#define SMF_MDV (SMF_NUM + GQ * NCHUNK * NC * IC)
#define SMF_A (SMF_MDV + GQ * NCHUNK * NC * IC)
#define SMF_P (SMF_A + GQ * NC * IC)
#define SMF_DSP (SMF_P + GQ * NC * IC)
#define SMF_RNQ (SMF_DSP + GQ * NC * IC)
#define SMF_STQ (SMF_RNQ + GQ * NC)
#define SMF_TOTAL (SMF_STQ + GQ * NC)

__global__ __launch_bounds__(1024) void routing_kernel(
    const __half* __restrict__ hmTh, const __half* __restrict__ hmPh,
    const float* __restrict__ meanA, const float* __restrict__ normA,
    const float* __restrict__ hq, float* __restrict__ out) {
  extern __shared__ float smem[];
  float2* tv = (float2*)(smem + SMF_TV);  // .x = tq, .y = v
  float* hv = smem + SMF_HV;
  float* num3 = smem + SMF_NUM;
  float* mdv3 = smem + SMF_MDV;
  float* a_s = smem + SMF_A;
  float* p_s = smem + SMF_P;
  float* dsp_s = smem + SMF_DSP;
  float* rnq = smem + SMF_RNQ;
  float* stq = smem + SMF_STQ;

  const int q0 = blockIdx.x * GQ;
  const int t = threadIdx.x;
  const int w = t >> 5, lane = t & 31;

  for (int j = t; j < GQ * NC * DP; j += 1024) {
    int qq = j / (NC * DP);
    int rem = j - qq * NC * DP;
    int c = rem / DP, d = rem - c * DP;
    float x = (d < DD) ? hq[(q0 + qq) * CDP + c * DD + d] : 0.f;
    tv[j] = make_float2(x, 0.f);
  }
  for (int j = t; j < GQ * NC * IC; j += 1024) a_s[j] = 0.f;
  __syncthreads();

  // prologue: initial norms (warps 0..9: qq=w/5, c=w%5)
  if (w < GQ * NC) {
    const int qq = w / NC, c = w - qq * NC;
    const float2* tvc = tv + qq * (NC * DP) + c * DP;
    float s = 0.f, s2 = 0.f;
    for (int d = lane; d < DD; d += 32) {
      float x = tvc[d].x;
      s += x;
      s2 += x * x;
    }
    s = warp_sum(s);
    s2 = warp_sum(s2);
    if (lane == 0) {
      float mean = s * (1.f / DD);
      rnq[qq * NC + c] = sqrtf(fmaxf(s2 - DD * mean * mean, 0.f));
      stq[qq * NC + c] = s;
    }
  }
  __syncthreads();

  for (int r = 0; r < 3; ++r) {
    // ---- phase A: 30 warps, each (qq, ch, c) ----
    if (w < GQ * NC * NCHUNK) {
      const int qq = w / (NC * NCHUNK);
      const int rem = w - qq * (NC * NCHUNK);
      const int ch = rem / NC;
      const int c = rem - ch * NC;
      const int d0 = ch * DCH, d1 = d0 + DCH;
      const uint2* base = (const uint2*)hmTh + c * DD * (IC / 4) + lane;
      const float2* tvc = tv + qq * NC * DP + c * DP;
      const int o = qq * NCHUNK * NC * IC + ch * (NC * IC) + c * IC + 4 * lane;
      if (r == 0) {
        float4 an = {0, 0, 0, 0};
#pragma unroll 3
        for (int d = d0; d < d1; ++d) {
          uint2 raw = base[d * (IC / 4)];
          float2 f01 = __half22float2(*(__half2*)&raw.x);
          float2 f23 = __half22float2(*(__half2*)&raw.y);
          float tx = tvc[d].x;
          an.x += f01.x * tx; an.y += f01.y * tx;
          an.z += f23.x * tx; an.w += f23.y * tx;
        }
        *(float4*)(num3 + o) = an;
      } else {
        float4 an = {0, 0, 0, 0}, av = {0, 0, 0, 0};
#pragma unroll 3
        for (int d = d0; d < d1; ++d) {
          uint2 raw = base[d * (IC / 4)];
          float2 f01 = __half22float2(*(__half2*)&raw.x);
          float2 f23 = __half22float2(*(__half2*)&raw.y);
          float2 tq = tvc[d];
          an.x += f01.x * tq.x; an.y += f01.y * tq.x;
          an.z += f23.x * tq.x; an.w += f23.y * tq.x;
          av.x += f01.x * tq.y; av.y += f01.y * tq.y;
          av.z += f23.x * tq.y; av.w += f23.y * tq.y;
        }
        *(float4*)(num3 + o) = an;
        *(float4*)(mdv3 + o) = av;
      }
    }
    __syncthreads();

    // ---- phase I: t < 256 ----
    if (t < GQ * IC) {
      const int qq = t >> 7, i = t & 127;
      const int qb = qq * NC * IC;
      const int q3 = qq * NCHUNK * NC * IC;
      float p[NC];
      if (r == 0) {
#pragma unroll
        for (int c = 0; c < NC; ++c) {
          int o = c * IC + i;
          float num = num3[q3 + o] + num3[q3 + NC * IC + o] +
                      num3[q3 + 2 * NC * IC + o] -
                      __ldg(meanA + o) * stq[qq * NC + c];
          float den = __ldg(normA + o) * rnq[qq * NC + c] + EPSF;
          float x = __fdividef(num, den);
          float e2 = __expf(2.f * x);
          p[c] = __fdividef(e2 - 1.f, e2 + 1.f);
          p_s[qb + o] = p[c];
          dsp_s[qb + o] = 0.2f + p[c];  // softmax of zeros
        }
      } else {
        float a[NC];
        float amax = -1e30f;
#pragma unroll
        for (int c = 0; c < NC; ++c) {
          int o = c * IC + i;
          float num = num3[q3 + o] + num3[q3 + NC * IC + o] +
                      num3[q3 + 2 * NC * IC + o] -
                      __ldg(meanA + o) * stq[qq * NC + c];
          float mdv = mdv3[q3 + o] + mdv3[q3 + NC * IC + o] +
                      mdv3[q3 + 2 * NC * IC + o];
          float po = p_s[qb + o];
          float av = a_s[qb + o] + po * mdv;
          a_s[qb + o] = av;
          a[c] = av;
          float den = __ldg(normA + o) * rnq[qq * NC + c] + EPSF;
          float x = __fdividef(num, den);
          float e2 = __expf(2.f * x);
          p[c] = __fdividef(e2 - 1.f, e2 + 1.f);
          p_s[qb + o] = p[c];
          amax = fmaxf(amax, av);
        }
        float es = 0.f, e[NC];
#pragma unroll
        for (int c = 0; c < NC; ++c) {
          e[c] = __expf(a[c] - amax);
          es += e[c];
        }
        float inv = __fdividef(1.f, es);
#pragma unroll
        for (int c = 0; c < NC; ++c) dsp_s[qb + c * IC + i] = e[c] * inv + p[c];
      }
    }
    __syncthreads();

    // ---- phase B: t < 800, thread per (qq,c,d2), single pass ----
    if (t < GQ * NC * (DP / 2)) {
      const int qq = t / (NC * (DP / 2));
      const int rem = t - qq * (NC * (DP / 2));
      const int c = rem / (DP / 2);
      const int d2 = rem - c * (DP / 2);
      const __half2* hp = (const __half2*)hmPh + c * (DP / 2) + d2;
      const float* wq = dsp_s + qq * NC * IC + c * IC;
      float ax = 0.f, ay = 0.f;
#pragma unroll 16
      for (int i = 0; i < IC; ++i) {
        float2 f = __half22float2(hp[i * (ROWP / 2)]);
        float g = wq[i];
        ax += f.x * g;
        ay += f.y * g;
      }
      hv[qq * NC * DP + c * DP + 2 * d2] = ax;
      hv[qq * NC * DP + c * DP + 2 * d2 + 1] = ay;
    }
    __syncthreads();

    // ---- phase S: squash + next tq + next norms (warps 0..9) ----
    if (w < GQ * NC) {
      const int qq = w / NC, c = w - qq * NC;
      const float* hvc = hv + qq * NC * DP + c * DP;
      float s2 = 0.f;
      for (int d = lane; d < DD; d += 32) {
        float x = hvc[d];
        s2 += x * x;
      }
      s2 = warp_sum(s2);
      float sc = s2 / ((1.f + s2) * sqrtf(s2 + EPSF));
      if (r < 2) {
        float2* tvc = tv + qq * NC * DP + c * DP;
        float s = 0.f, sq = 0.f;
        for (int d = lane; d < DD; d += 32) {
          float vd = hvc[d] * sc;
          float x = (tvc[d].x + vd) * 0.5f;
          tvc[d] = make_float2(x, vd);
          s += x;
          sq += x * x;
        }
        s = warp_sum(s);
        sq = warp_sum(sq);
        if (lane == 0) {
          float mean = s * (1.f / DD);
          rnq[qq * NC + c] = sqrtf(fmaxf(sq - DD * mean * mean, 0.f));
          stq[qq * NC + c] = s;
        }
      } else {
        for (int d = lane; d < DD; d += 32)
          out[(q0 + qq) * CD + c * DD + d] = hvc[d] * sc;
      }
    }
    __syncthreads();
  }
}

// ---------------------------------------------------------------------------
extern "C" void kernel_launch(void* const* d_in, const int* in_sizes, int n_in,
                              void* d_out, int out_size) {
  const float *m = nullptr, *q = nullptr, *W = nullptr, *b = nullptr;
  for (int i = 0; i < n_in; ++i) {
    switch (in_sizes[i]) {
      case IC * KD: m = (const float*)d_in[i]; break;
      case NQV * KD: q = (const float*)d_in[i]; break;
      case KD * CD: W = (const float*)d_in[i]; break;
      case CD: b = (const float*)d_in[i]; break;
      default: break;
    }
  }
  float* out = (float*)d_out;

  void *p_hm, *p_hq, *p_hmTh, *p_hmPh, *p_mean, *p_norm, *p_wp;
  cudaGetSymbolAddress(&p_hm, g_hm);
  cudaGetSymbolAddress(&p_hq, g_hq);
  cudaGetSymbolAddress(&p_hmTh, g_hmTh);
  cudaGetSymbolAddress(&p_hmPh, g_hmPh);
  cudaGetSymbolAddress(&p_mean, g_mean);
  cudaGetSymbolAddress(&p_norm, g_norm);
  cudaGetSymbolAddress(&p_wp, g_Wp);

  static bool attr_set = false;
  if (!attr_set) {
    cudaFuncSetAttribute(routing_kernel,
                         cudaFuncAttributeMaxDynamicSharedMemorySize,
                         SMF_TOTAL * 4);
    attr_set = true;
  }

  wpad_kernel<<<(KD * CDP + 255) / 256, 256>>>(W, (float*)p_wp);

  dim3 gg(CDP / BN, (IC + NQV) / BM);
  gemm_kernel<<<gg, 256>>>(m, q, (const float*)p_wp, b, (float*)p_hm,
                           (float*)p_hq);

  prep_kernel<<<180, 256>>>((const float*)p_hm, (__half*)p_hmPh,
                            (__half*)p_hmTh, (float*)p_mean, (float*)p_norm);

  routing_kernel<<<NQV / GQ, 1024, SMF_TOTAL * 4>>>(
      (const __half*)p_hmTh, (const __half*)p_hmPh, (const float*)p_mean,
      (const float*)p_norm, (const float*)p_hq, out);
}